// round 14
// baseline (speedup 1.0000x reference)
#include <cuda_runtime.h>

// NeuralODEClassifier, two kernels.
// K1 (ODE): R13 exactly — quad lanes, 2 elems/thread, batched-rcp sigmoid
//   with fma-fold, f32x2 packed MLP + packed accumulator. occ 8, single wave.
// K2 (classifier) v2: 4 lanes/elem (13.85 warps/SMSP, 4x v1). Lane q builds
//   h1 slice k in [16q,16q+16) into sH1 (its own later read slice), owns
//   outputs j = 4*jj+q. Pad-68 rows make Wc2T reads (drow=1 -> disjoint 16B
//   spans) and sH1 reads (delta=272B -> 8 disjoint spans) bank-conflict-free.
//
// tanh(z) = 1 - 2/(2^(C*z)+1), C = 2*log2(e); W1/b1 prescaled by C, the
// (1-2r) fold absorbed into W2 (v = -2*W2, S = colsum(W2)+b2).

#define H 64
#define TT 64
#define NCLS 3
#define BMAX 65536

typedef unsigned long long u64;

__device__ float g_yT[BMAX * 2];

__device__ __forceinline__ float fast_ex2(float x) {
    float r; asm("ex2.approx.f32 %0, %1;" : "=f"(r) : "f"(x)); return r;
}
__device__ __forceinline__ float fast_rcp(float x) {
    float r; asm("rcp.approx.f32 %0, %1;" : "=f"(r) : "f"(x)); return r;
}
__device__ __forceinline__ u64 pk2(float lo, float hi) {
    u64 r; asm("mov.b64 %0, {%1, %2};" : "=l"(r) : "f"(lo), "f"(hi)); return r;
}
__device__ __forceinline__ void unpk2(u64 v, float& lo, float& hi) {
    asm("mov.b64 {%0, %1}, %2;" : "=f"(lo), "=f"(hi) : "l"(v));
}
__device__ __forceinline__ u64 fma2(u64 a, u64 b, u64 c) {
    u64 d; asm("fma.rn.f32x2 %0, %1, %2, %3;" : "=l"(d) : "l"(a), "l"(b), "l"(c));
    return d;
}

// unit u = q*16 + g*4 + c  ->  float slot ((g*4+q)*4 + c).
// For fixed g the 4 quad-lanes read 4 consecutive 16B chunks: conflict-free.
#define PK(g, q, c) (((g) * 4 + (q)) * 4 + (c))

// ---------------------------------------------------------------- K1: ODE ---
__global__ __launch_bounds__(128, 8)
void node_ode_kernel(
    const float* __restrict__ y0g,  const float* __restrict__ tg,
    const float* __restrict__ W1,   const float* __restrict__ b1,
    const float* __restrict__ W2,   const float* __restrict__ b2,
    int B)
{
    __shared__ __align__(16) float sWA[H];      // W1 row0 * C, packed
    __shared__ __align__(16) float sWB[H];      // W1 row1 * C, packed
    __shared__ __align__(16) float sBB[H];      // b1  * C, packed
    __shared__ __align__(16) float sVV[H * 2];  // {-2*W2[u][0], -2*W2[u][1]} per unit, packed
    __shared__ float sS[2];
    __shared__ float sdt[TT - 1];

    const float C = 2.88539008177792681472f;    // 2*log2(e)
    const int tid = threadIdx.x;

    if (tid < H) {
        int u = tid;
        int q = u >> 4, r = u & 15, g = r >> 2, c = r & 3;
        int p = PK(g, q, c);
        sWA[p] = W1[u] * C;
        sWB[p] = W1[H + u] * C;
        sBB[p] = b1[u] * C;
        sVV[p * 2 + 0] = -2.0f * W2[u * 2 + 0];
        sVV[p * 2 + 1] = -2.0f * W2[u * 2 + 1];
    }
    if (tid >= H && tid < H + 2) {
        int c = tid - H;
        float s = b2[c];
        #pragma unroll 8
        for (int j = 0; j < H; j++) s += W2[j * 2 + c];
        sS[c] = s;
    }
    for (int i = tid; i < TT - 1; i += 128)
        sdt[i] = tg[i + 1] - tg[i];
    __syncthreads();

    const int gid = blockIdx.x * 128 + tid;
    const int eA = gid >> 2;           // first element
    const int q  = gid & 3;            // quad slot
    const int half = B >> 1;
    if (eA >= half) return;
    const int eB = eA + half;          // second element

    float yaA = y0g[eA * 2 + 0], ybA = y0g[eA * 2 + 1];
    float yaB = y0g[eB * 2 + 0], ybB = y0g[eB * 2 + 1];
    const float S0 = sS[0], S1 = sS[1];

    for (int s = 0; s < TT - 1; s++) {
        const float dt = sdt[s];
        const u64 pAa = pk2(yaA, yaA), pAb = pk2(ybA, ybA);
        const u64 pBa = pk2(yaB, yaB), pBb = pk2(ybB, ybB);
        u64 accA = 0, accB = 0;        // each = {acc0, acc1}

        #pragma unroll
        for (int g = 0; g < 4; g++) {
            const int base = PK(g, q, 0);
            const ulonglong2 WA = *(const ulonglong2*)&sWA[base];
            const ulonglong2 WB = *(const ulonglong2*)&sWB[base];
            const ulonglong2 BB = *(const ulonglong2*)&sBB[base];
            const ulonglong2 Vp01 = *(const ulonglong2*)&sVV[base * 2];
            const ulonglong2 Vp23 = *(const ulonglong2*)&sVV[base * 2 + 4];

            // element A
            {
                u64 w01 = fma2(pAa, WA.x, fma2(pAb, WB.x, BB.x));
                u64 w23 = fma2(pAa, WA.y, fma2(pAb, WB.y, BB.y));
                float w0, w1, w2, w3;
                unpk2(w01, w0, w1);
                unpk2(w23, w2, w3);
                w0 = fminf(w0, 30.0f); w1 = fminf(w1, 30.0f);
                w2 = fminf(w2, 30.0f); w3 = fminf(w3, 30.0f);
                float E0 = fast_ex2(w0), E1 = fast_ex2(w1);
                float E2 = fast_ex2(w2), E3 = fast_ex2(w3);
                float a0 = E0 + 1.0f, a2 = E2 + 1.0f;
                float p01 = fmaf(a0, E1, a0);       // a0*(E1+1)
                float p23 = fmaf(a2, E3, a2);       // a2*(E3+1)
                float rinv = fast_rcp(p01 * p23);
                float q01 = rinv * p23, q23 = rinv * p01;
                float r1 = q01 * a0, r0 = fmaf(q01, E1, q01);
                float r3 = q23 * a2, r2 = fmaf(q23, E3, q23);
                accA = fma2(pk2(r0, r0), Vp01.x, accA);
                accA = fma2(pk2(r1, r1), Vp01.y, accA);
                accA = fma2(pk2(r2, r2), Vp23.x, accA);
                accA = fma2(pk2(r3, r3), Vp23.y, accA);
            }
            // element B
            {
                u64 w01 = fma2(pBa, WA.x, fma2(pBb, WB.x, BB.x));
                u64 w23 = fma2(pBa, WA.y, fma2(pBb, WB.y, BB.y));
                float w0, w1, w2, w3;
                unpk2(w01, w0, w1);
                unpk2(w23, w2, w3);
                w0 = fminf(w0, 30.0f); w1 = fminf(w1, 30.0f);
                w2 = fminf(w2, 30.0f); w3 = fminf(w3, 30.0f);
                float E0 = fast_ex2(w0), E1 = fast_ex2(w1);
                float E2 = fast_ex2(w2), E3 = fast_ex2(w3);
                float a0 = E0 + 1.0f, a2 = E2 + 1.0f;
                float p01 = fmaf(a0, E1, a0);
                float p23 = fmaf(a2, E3, a2);
                float rinv = fast_rcp(p01 * p23);
                float q01 = rinv * p23, q23 = rinv * p01;
                float r1 = q01 * a0, r0 = fmaf(q01, E1, q01);
                float r3 = q23 * a2, r2 = fmaf(q23, E3, q23);
                accB = fma2(pk2(r0, r0), Vp01.x, accB);
                accB = fma2(pk2(r1, r1), Vp01.y, accB);
                accB = fma2(pk2(r2, r2), Vp23.x, accB);
                accB = fma2(pk2(r3, r3), Vp23.y, accB);
            }
        }

        float accA0, accA1, accB0, accB1;
        unpk2(accA, accA0, accA1);
        unpk2(accB, accB0, accB1);
        accA0 += __shfl_xor_sync(0xffffffffu, accA0, 1);
        accA0 += __shfl_xor_sync(0xffffffffu, accA0, 2);
        accA1 += __shfl_xor_sync(0xffffffffu, accA1, 1);
        accA1 += __shfl_xor_sync(0xffffffffu, accA1, 2);
        accB0 += __shfl_xor_sync(0xffffffffu, accB0, 1);
        accB0 += __shfl_xor_sync(0xffffffffu, accB0, 2);
        accB1 += __shfl_xor_sync(0xffffffffu, accB1, 1);
        accB1 += __shfl_xor_sync(0xffffffffu, accB1, 2);

        yaA = fmaf(dt, S0 + accA0, yaA);   // identical across the quad
        ybA = fmaf(dt, S1 + accA1, ybA);
        yaB = fmaf(dt, S0 + accB0, yaB);
        ybB = fmaf(dt, S1 + accB1, ybB);
    }

    if (q == 0) {
        g_yT[eA * 2 + 0] = yaA;
        g_yT[eA * 2 + 1] = ybA;
        g_yT[eB * 2 + 0] = yaB;
        g_yT[eB * 2 + 1] = ybB;
    }
}

// ------------------------------------------------------ K2: classifier v2 ---
// 4 lanes per element. Lane q: builds h1[16q..16q+16) into sH1, owns outputs
// j = 4*jj + q. Pad-68 rows -> conflict-free Wc2T and sH1 access patterns.
#define CPAD 68

__global__ __launch_bounds__(128, 7)
void node_cls_kernel(
    const float* __restrict__ Wc1,  const float* __restrict__ bc1,
    const float* __restrict__ Wc2,  const float* __restrict__ bc2,
    const float* __restrict__ Wc3,  const float* __restrict__ bc3,
    float* __restrict__ out, int B)
{
    __shared__ __align__(16) float sWc1A[H], sWc1B[H], sbc1[H], sbc2[H];
    __shared__ __align__(16) float sWc2T[H][CPAD];  // [out_j][in_k], padded
    __shared__ __align__(16) float4 sWc3[H];        // {w0,w1,w2,0}
    __shared__ float sbc3[NCLS];
    __shared__ __align__(16) float sH1[32][CPAD];   // 32 elems/CTA

    const int tid = threadIdx.x;
    if (tid < H) {
        sWc1A[tid] = Wc1[tid];
        sWc1B[tid] = Wc1[H + tid];
        sbc1[tid]  = bc1[tid];
        sbc2[tid]  = bc2[tid];
        sWc3[tid]  = make_float4(Wc3[tid * 3 + 0], Wc3[tid * 3 + 1],
                                 Wc3[tid * 3 + 2], 0.0f);
    }
    if (tid < NCLS) sbc3[tid] = bc3[tid];
    for (int i = tid; i < H * H; i += 128) {
        int k = i >> 6, j = i & 63;      // Wc2 row-major [k][j]
        sWc2T[j][k] = Wc2[i];
    }
    __syncthreads();

    const int gid = blockIdx.x * 128 + tid;
    const int e = gid >> 2;              // element
    const int q = gid & 3;               // quad slot
    const int eloc = tid >> 2;           // element row in sH1
    if (e >= B) return;

    const float ya = g_yT[e * 2 + 0];
    const float yb = g_yT[e * 2 + 1];

    // h1 slice k in [16q, 16q+16) — exactly the slice this lane reads later
    const int k0 = 16 * q;
    #pragma unroll
    for (int i = 0; i < 16; i += 4) {
        const float4 wa = *(const float4*)&sWc1A[k0 + i];
        const float4 wb = *(const float4*)&sWc1B[k0 + i];
        const float4 bb = *(const float4*)&sbc1[k0 + i];
        float4 h;
        h.x = fmaxf(fmaf(ya, wa.x, fmaf(yb, wb.x, bb.x)), 0.0f);
        h.y = fmaxf(fmaf(ya, wa.y, fmaf(yb, wb.y, bb.y)), 0.0f);
        h.z = fmaxf(fmaf(ya, wa.z, fmaf(yb, wb.z, bb.z)), 0.0f);
        h.w = fmaxf(fmaf(ya, wa.w, fmaf(yb, wb.w, bb.w)), 0.0f);
        *(float4*)&sH1[eloc][k0 + i] = h;
    }
    __syncwarp();                        // quad lanes share a warp

    // my 16 output units: j = 4*jj + q
    float acc[16];
    #pragma unroll
    for (int jj = 0; jj < 16; jj++) acc[jj] = sbc2[4 * jj + q];

    #pragma unroll 4
    for (int k = 0; k < H; k += 4) {
        const float4 hk = *(const float4*)&sH1[eloc][k];
        #pragma unroll
        for (int jj = 0; jj < 16; jj++) {
            const float4 w = *(const float4*)&sWc2T[4 * jj + q][k];
            acc[jj] = fmaf(hk.w, w.w,
                      fmaf(hk.z, w.z,
                      fmaf(hk.y, w.y,
                      fmaf(hk.x, w.x, acc[jj]))));
        }
    }

    float o0 = 0.f, o1 = 0.f, o2 = 0.f;
    #pragma unroll
    for (int jj = 0; jj < 16; jj++) {
        const float hv = fmaxf(acc[jj], 0.0f);
        const float4 wc = sWc3[4 * jj + q];
        o0 = fmaf(hv, wc.x, o0);
        o1 = fmaf(hv, wc.y, o1);
        o2 = fmaf(hv, wc.z, o2);
    }
    o0 += __shfl_xor_sync(0xffffffffu, o0, 1);
    o0 += __shfl_xor_sync(0xffffffffu, o0, 2);
    o1 += __shfl_xor_sync(0xffffffffu, o1, 1);
    o1 += __shfl_xor_sync(0xffffffffu, o1, 2);
    o2 += __shfl_xor_sync(0xffffffffu, o2, 1);
    o2 += __shfl_xor_sync(0xffffffffu, o2, 2);

    if (q == 0) {
        out[e * 3 + 0] = o0 + sbc3[0];
        out[e * 3 + 1] = o1 + sbc3[1];
        out[e * 3 + 2] = o2 + sbc3[2];
    }
}

extern "C" void kernel_launch(void* const* d_in, const int* in_sizes, int n_in,
                              void* d_out, int out_size) {
    const float* y0  = (const float*)d_in[0];
    const float* t   = (const float*)d_in[1];
    const float* W1  = (const float*)d_in[2];
    const float* b1  = (const float*)d_in[3];
    const float* W2  = (const float*)d_in[4];
    const float* b2  = (const float*)d_in[5];
    const float* Wc1 = (const float*)d_in[6];
    const float* bc1 = (const float*)d_in[7];
    const float* Wc2 = (const float*)d_in[8];
    const float* bc2 = (const float*)d_in[9];
    const float* Wc3 = (const float*)d_in[10];
    const float* bc3 = (const float*)d_in[11];
    float* out = (float*)d_out;

    const int B = in_sizes[0] / 2;
    const long long thOde = (long long)B * 2;   // 4 lanes/elem, 2 elems/thread
    const long long thCls = (long long)B * 4;   // 4 lanes/elem
    node_ode_kernel<<<(int)((thOde + 127) / 128), 128>>>(y0, t, W1, b1, W2, b2, B);
    node_cls_kernel<<<(int)((thCls + 127) / 128), 128>>>(Wc1, bc1, Wc2, bc2,
                                                         Wc3, bc3, out, B);
}

// round 15
// speedup vs baseline: 1.0716x; 1.0716x over previous
#include <cuda_runtime.h>

// NeuralODEClassifier, two kernels.
// K1 (ODE): R13 + register staging of the loop-invariant V-pairs for groups
//   g=0,1 (8 u64 = 16 regs) -> LDS.128 per thread-step 20 -> 16. Quad lanes,
//   16 units/lane, 2 elems/thread, batched-rcp sigmoid with fma-fold, f32x2
//   packed MLP + packed accumulator. occ 8 (64-reg cap), 1024 CTAs, 1 wave.
// K2 (classifier): v1 verbatim — 1 thread/elem, block 128, Wc2 transposed in
//   shared, warp-broadcast reads (proven 33us).
//
// tanh(z) = 1 - 2/(2^(C*z)+1), C = 2*log2(e); W1/b1 prescaled by C, the
// (1-2r) fold absorbed into W2 (v = -2*W2, S = colsum(W2)+b2).

#define H 64
#define TT 64
#define NCLS 3
#define BMAX 65536

typedef unsigned long long u64;

__device__ float g_yT[BMAX * 2];

__device__ __forceinline__ float fast_ex2(float x) {
    float r; asm("ex2.approx.f32 %0, %1;" : "=f"(r) : "f"(x)); return r;
}
__device__ __forceinline__ float fast_rcp(float x) {
    float r; asm("rcp.approx.f32 %0, %1;" : "=f"(r) : "f"(x)); return r;
}
__device__ __forceinline__ u64 pk2(float lo, float hi) {
    u64 r; asm("mov.b64 %0, {%1, %2};" : "=l"(r) : "f"(lo), "f"(hi)); return r;
}
__device__ __forceinline__ void unpk2(u64 v, float& lo, float& hi) {
    asm("mov.b64 {%0, %1}, %2;" : "=f"(lo), "=f"(hi) : "l"(v));
}
__device__ __forceinline__ u64 fma2(u64 a, u64 b, u64 c) {
    u64 d; asm("fma.rn.f32x2 %0, %1, %2, %3;" : "=l"(d) : "l"(a), "l"(b), "l"(c));
    return d;
}

// unit u = q*16 + g*4 + c  ->  float slot ((g*4+q)*4 + c).
// For fixed g the 4 quad-lanes read 4 consecutive 16B chunks: conflict-free.
#define PK(g, q, c) (((g) * 4 + (q)) * 4 + (c))

// ---------------------------------------------------------------- K1: ODE ---
__global__ __launch_bounds__(128, 8)
void node_ode_kernel(
    const float* __restrict__ y0g,  const float* __restrict__ tg,
    const float* __restrict__ W1,   const float* __restrict__ b1,
    const float* __restrict__ W2,   const float* __restrict__ b2,
    int B)
{
    __shared__ __align__(16) float sWA[H];      // W1 row0 * C, packed
    __shared__ __align__(16) float sWB[H];      // W1 row1 * C, packed
    __shared__ __align__(16) float sBB[H];      // b1  * C, packed
    __shared__ __align__(16) float sVV[H * 2];  // {-2*W2[u][0], -2*W2[u][1]} per unit, packed
    __shared__ float sS[2];
    __shared__ float sdt[TT - 1];

    const float C = 2.88539008177792681472f;    // 2*log2(e)
    const int tid = threadIdx.x;

    if (tid < H) {
        int u = tid;
        int q = u >> 4, r = u & 15, g = r >> 2, c = r & 3;
        int p = PK(g, q, c);
        sWA[p] = W1[u] * C;
        sWB[p] = W1[H + u] * C;
        sBB[p] = b1[u] * C;
        sVV[p * 2 + 0] = -2.0f * W2[u * 2 + 0];
        sVV[p * 2 + 1] = -2.0f * W2[u * 2 + 1];
    }
    if (tid >= H && tid < H + 2) {
        int c = tid - H;
        float s = b2[c];
        #pragma unroll 8
        for (int j = 0; j < H; j++) s += W2[j * 2 + c];
        sS[c] = s;
    }
    for (int i = tid; i < TT - 1; i += 128)
        sdt[i] = tg[i + 1] - tg[i];
    __syncthreads();

    const int gid = blockIdx.x * 128 + tid;
    const int eA = gid >> 2;           // first element
    const int q  = gid & 3;            // quad slot
    const int half = B >> 1;
    if (eA >= half) return;
    const int eB = eA + half;          // second element

    float yaA = y0g[eA * 2 + 0], ybA = y0g[eA * 2 + 1];
    float yaB = y0g[eB * 2 + 0], ybB = y0g[eB * 2 + 1];
    const float S0 = sS[0], S1 = sS[1];

    // Register-stage the loop-invariant V pairs for groups 0 and 1
    // (8 u64 = 16 regs): removes 4 LDS.128 per thread-step.
    u64 Vst[8];
    #pragma unroll
    for (int g = 0; g < 2; g++) {
        const int base = PK(g, q, 0);
        const ulonglong2 a = *(const ulonglong2*)&sVV[base * 2];
        const ulonglong2 b = *(const ulonglong2*)&sVV[base * 2 + 4];
        Vst[g * 4 + 0] = a.x; Vst[g * 4 + 1] = a.y;
        Vst[g * 4 + 2] = b.x; Vst[g * 4 + 3] = b.y;
    }

    for (int s = 0; s < TT - 1; s++) {
        const float dt = sdt[s];
        const u64 pAa = pk2(yaA, yaA), pAb = pk2(ybA, ybA);
        const u64 pBa = pk2(yaB, yaB), pBb = pk2(ybB, ybB);
        u64 accA = 0, accB = 0;        // each = {acc0, acc1}

        #pragma unroll
        for (int g = 0; g < 4; g++) {
            const int base = PK(g, q, 0);
            const ulonglong2 WA = *(const ulonglong2*)&sWA[base];
            const ulonglong2 WB = *(const ulonglong2*)&sWB[base];
            const ulonglong2 BB = *(const ulonglong2*)&sBB[base];
            u64 V01x, V01y, V23x, V23y;
            if (g < 2) {               // resolved at compile time (unrolled)
                V01x = Vst[g * 4 + 0]; V01y = Vst[g * 4 + 1];
                V23x = Vst[g * 4 + 2]; V23y = Vst[g * 4 + 3];
            } else {
                const ulonglong2 Vp01 = *(const ulonglong2*)&sVV[base * 2];
                const ulonglong2 Vp23 = *(const ulonglong2*)&sVV[base * 2 + 4];
                V01x = Vp01.x; V01y = Vp01.y;
                V23x = Vp23.x; V23y = Vp23.y;
            }

            // element A
            {
                u64 w01 = fma2(pAa, WA.x, fma2(pAb, WB.x, BB.x));
                u64 w23 = fma2(pAa, WA.y, fma2(pAb, WB.y, BB.y));
                float w0, w1, w2, w3;
                unpk2(w01, w0, w1);
                unpk2(w23, w2, w3);
                w0 = fminf(w0, 30.0f); w1 = fminf(w1, 30.0f);
                w2 = fminf(w2, 30.0f); w3 = fminf(w3, 30.0f);
                float E0 = fast_ex2(w0), E1 = fast_ex2(w1);
                float E2 = fast_ex2(w2), E3 = fast_ex2(w3);
                float a0 = E0 + 1.0f, a2 = E2 + 1.0f;
                float p01 = fmaf(a0, E1, a0);       // a0*(E1+1)
                float p23 = fmaf(a2, E3, a2);       // a2*(E3+1)
                float rinv = fast_rcp(p01 * p23);
                float q01 = rinv * p23, q23 = rinv * p01;
                float r1 = q01 * a0, r0 = fmaf(q01, E1, q01);
                float r3 = q23 * a2, r2 = fmaf(q23, E3, q23);
                accA = fma2(pk2(r0, r0), V01x, accA);
                accA = fma2(pk2(r1, r1), V01y, accA);
                accA = fma2(pk2(r2, r2), V23x, accA);
                accA = fma2(pk2(r3, r3), V23y, accA);
            }
            // element B
            {
                u64 w01 = fma2(pBa, WA.x, fma2(pBb, WB.x, BB.x));
                u64 w23 = fma2(pBa, WA.y, fma2(pBb, WB.y, BB.y));
                float w0, w1, w2, w3;
                unpk2(w01, w0, w1);
                unpk2(w23, w2, w3);
                w0 = fminf(w0, 30.0f); w1 = fminf(w1, 30.0f);
                w2 = fminf(w2, 30.0f); w3 = fminf(w3, 30.0f);
                float E0 = fast_ex2(w0), E1 = fast_ex2(w1);
                float E2 = fast_ex2(w2), E3 = fast_ex2(w3);
                float a0 = E0 + 1.0f, a2 = E2 + 1.0f;
                float p01 = fmaf(a0, E1, a0);
                float p23 = fmaf(a2, E3, a2);
                float rinv = fast_rcp(p01 * p23);
                float q01 = rinv * p23, q23 = rinv * p01;
                float r1 = q01 * a0, r0 = fmaf(q01, E1, q01);
                float r3 = q23 * a2, r2 = fmaf(q23, E3, q23);
                accB = fma2(pk2(r0, r0), V01x, accB);
                accB = fma2(pk2(r1, r1), V01y, accB);
                accB = fma2(pk2(r2, r2), V23x, accB);
                accB = fma2(pk2(r3, r3), V23y, accB);
            }
        }

        float accA0, accA1, accB0, accB1;
        unpk2(accA, accA0, accA1);
        unpk2(accB, accB0, accB1);
        accA0 += __shfl_xor_sync(0xffffffffu, accA0, 1);
        accA0 += __shfl_xor_sync(0xffffffffu, accA0, 2);
        accA1 += __shfl_xor_sync(0xffffffffu, accA1, 1);
        accA1 += __shfl_xor_sync(0xffffffffu, accA1, 2);
        accB0 += __shfl_xor_sync(0xffffffffu, accB0, 1);
        accB0 += __shfl_xor_sync(0xffffffffu, accB0, 2);
        accB1 += __shfl_xor_sync(0xffffffffu, accB1, 1);
        accB1 += __shfl_xor_sync(0xffffffffu, accB1, 2);

        yaA = fmaf(dt, S0 + accA0, yaA);   // identical across the quad
        ybA = fmaf(dt, S1 + accA1, ybA);
        yaB = fmaf(dt, S0 + accB0, yaB);
        ybB = fmaf(dt, S1 + accB1, ybB);
    }

    if (q == 0) {
        g_yT[eA * 2 + 0] = yaA;
        g_yT[eA * 2 + 1] = ybA;
        g_yT[eB * 2 + 0] = yaB;
        g_yT[eB * 2 + 1] = ybB;
    }
}

// --------------------------------------------------------- K2: classifier ---
// v1: 1 thread/elem, block 128, warp-broadcast shared reads (proven 33us).
__global__ __launch_bounds__(128, 4)
void node_cls_kernel(
    const float* __restrict__ Wc1,  const float* __restrict__ bc1,
    const float* __restrict__ Wc2,  const float* __restrict__ bc2,
    const float* __restrict__ Wc3,  const float* __restrict__ bc3,
    float* __restrict__ out, int B)
{
    __shared__ __align__(16) float sWc1A[H], sWc1B[H], sbc1[H];
    __shared__ __align__(16) float sWc2T[H][H];  // [out_j][in_k]
    __shared__ __align__(16) float sbc2[H];
    __shared__ __align__(16) float4 sWc3[H];     // {w0,w1,w2,0}
    __shared__ float sbc3[NCLS];

    const int tid = threadIdx.x;
    if (tid < H) {
        sWc1A[tid] = Wc1[tid];
        sWc1B[tid] = Wc1[H + tid];
        sbc1[tid]  = bc1[tid];
        sbc2[tid]  = bc2[tid];
        sWc3[tid]  = make_float4(Wc3[tid * 3 + 0], Wc3[tid * 3 + 1],
                                 Wc3[tid * 3 + 2], 0.0f);
    }
    if (tid < NCLS) sbc3[tid] = bc3[tid];
    for (int i = tid; i < H * H; i += 128) {
        sWc2T[i & 63][i >> 6] = Wc2[i];
    }
    __syncthreads();

    const int idx = blockIdx.x * 128 + tid;
    if (idx >= B) return;

    const float ya = g_yT[idx * 2 + 0];
    const float yb = g_yT[idx * 2 + 1];

    float h1[H];
    #pragma unroll
    for (int j = 0; j < H; j++)
        h1[j] = fmaxf(fmaf(ya, sWc1A[j], fmaf(yb, sWc1B[j], sbc1[j])), 0.0f);

    float o0 = sbc3[0], o1 = sbc3[1], o2 = sbc3[2];
    for (int j = 0; j < H; j++) {
        float s0 = sbc2[j], s1 = 0.f, s2 = 0.f, s3 = 0.f;
        #pragma unroll
        for (int k = 0; k < H; k += 4) {
            const float4 w = *(const float4*)&sWc2T[j][k];
            s0 = fmaf(h1[k + 0], w.x, s0);
            s1 = fmaf(h1[k + 1], w.y, s1);
            s2 = fmaf(h1[k + 2], w.z, s2);
            s3 = fmaf(h1[k + 3], w.w, s3);
        }
        float s = fmaxf((s0 + s1) + (s2 + s3), 0.0f);
        const float4 wc = sWc3[j];
        o0 = fmaf(s, wc.x, o0);
        o1 = fmaf(s, wc.y, o1);
        o2 = fmaf(s, wc.z, o2);
    }

    out[idx * 3 + 0] = o0;
    out[idx * 3 + 1] = o1;
    out[idx * 3 + 2] = o2;
}

extern "C" void kernel_launch(void* const* d_in, const int* in_sizes, int n_in,
                              void* d_out, int out_size) {
    const float* y0  = (const float*)d_in[0];
    const float* t   = (const float*)d_in[1];
    const float* W1  = (const float*)d_in[2];
    const float* b1  = (const float*)d_in[3];
    const float* W2  = (const float*)d_in[4];
    const float* b2  = (const float*)d_in[5];
    const float* Wc1 = (const float*)d_in[6];
    const float* bc1 = (const float*)d_in[7];
    const float* Wc2 = (const float*)d_in[8];
    const float* bc2 = (const float*)d_in[9];
    const float* Wc3 = (const float*)d_in[10];
    const float* bc3 = (const float*)d_in[11];
    float* out = (float*)d_out;

    const int B = in_sizes[0] / 2;
    const long long thOde = (long long)B * 2;   // 4 lanes/elem, 2 elems/thread
    node_ode_kernel<<<(int)((thOde + 127) / 128), 128>>>(y0, t, W1, b1, W2, b2, B);
    node_cls_kernel<<<(B + 127) / 128, 128>>>(Wc1, bc1, Wc2, bc2, Wc3, bc3, out, B);
}

// round 17
// speedup vs baseline: 1.1213x; 1.0464x over previous
#include <cuda_runtime.h>

// NeuralODEClassifier — single fused kernel (R15 ODE + in-kernel classifier).
// ODE: quad = 4 lanes/elem, 16 units/lane, 2 elems/thread, batched-rcp
//   sigmoid with fma-fold, f32x2 packed MLP + packed accumulator, V-pairs for
//   g=0,1 register-staged. occ 7 (73-reg cap), 1024 CTAs, single wave.
// Classifier fused at tail (runs at 28 warps/SM instead of a separate
//   launch at 13.8): lane q builds h1[16q..16q+16) into sH1 (pad-68,
//   conflict-free), owns outputs j=4jj+q from sWc2T (pad-68), quad-reduces
//   logits by shuffle. Weights staged once per CTA before the step loop.
//
// tanh(z) = 1 - 2/(2^(C*z)+1), C = 2*log2(e); W1/b1 prescaled by C, the
// (1-2r) fold absorbed into W2 (v = -2*W2, S = colsum(W2)+b2).

#define H 64
#define TT 64
#define NCLS 3
#define CPAD 68

typedef unsigned long long u64;

__device__ __forceinline__ float fast_ex2(float x) {
    float r; asm("ex2.approx.f32 %0, %1;" : "=f"(r) : "f"(x)); return r;
}
__device__ __forceinline__ float fast_rcp(float x) {
    float r; asm("rcp.approx.f32 %0, %1;" : "=f"(r) : "f"(x)); return r;
}
__device__ __forceinline__ u64 pk2(float lo, float hi) {
    u64 r; asm("mov.b64 %0, {%1, %2};" : "=l"(r) : "f"(lo), "f"(hi)); return r;
}
__device__ __forceinline__ void unpk2(u64 v, float& lo, float& hi) {
    asm("mov.b64 {%0, %1}, %2;" : "=f"(lo), "=f"(hi) : "l"(v));
}
__device__ __forceinline__ u64 fma2(u64 a, u64 b, u64 c) {
    u64 d; asm("fma.rn.f32x2 %0, %1, %2, %3;" : "=l"(d) : "l"(a), "l"(b), "l"(c));
    return d;
}

// unit u = q*16 + g*4 + c  ->  float slot ((g*4+q)*4 + c).
#define PK(g, q, c) (((g) * 4 + (q)) * 4 + (c))

__global__ __launch_bounds__(128, 7)
void node_fused_kernel(
    const float* __restrict__ y0g,  const float* __restrict__ tg,
    const float* __restrict__ W1,   const float* __restrict__ b1,
    const float* __restrict__ W2,   const float* __restrict__ b2,
    const float* __restrict__ Wc1,  const float* __restrict__ bc1,
    const float* __restrict__ Wc2,  const float* __restrict__ bc2,
    const float* __restrict__ Wc3,  const float* __restrict__ bc3,
    float* __restrict__ out, int B)
{
    // --- ODE weights ---
    __shared__ __align__(16) float sWA[H];
    __shared__ __align__(16) float sWB[H];
    __shared__ __align__(16) float sBB[H];
    __shared__ __align__(16) float sVV[H * 2];
    __shared__ float sS[2];
    __shared__ float sdt[TT - 1];
    // --- classifier weights ---
    __shared__ __align__(16) float sWc1A[H], sWc1B[H], sbc1[H], sbc2[H];
    __shared__ __align__(16) float sWc2T[H][CPAD];  // [out_j][in_k], padded
    __shared__ __align__(16) float4 sWc3[H];        // {w0,w1,w2,0}
    __shared__ float sbc3[NCLS];
    __shared__ __align__(16) float sH1[32][CPAD];   // 32 element rows per CTA

    const float C = 2.88539008177792681472f;        // 2*log2(e)
    const int tid = threadIdx.x;

    if (tid < H) {
        int u = tid;
        int q = u >> 4, r = u & 15, g = r >> 2, c = r & 3;
        int p = PK(g, q, c);
        sWA[p] = W1[u] * C;
        sWB[p] = W1[H + u] * C;
        sBB[p] = b1[u] * C;
        sVV[p * 2 + 0] = -2.0f * W2[u * 2 + 0];
        sVV[p * 2 + 1] = -2.0f * W2[u * 2 + 1];
        sWc1A[u] = Wc1[u];
        sWc1B[u] = Wc1[H + u];
        sbc1[u]  = bc1[u];
        sbc2[u]  = bc2[u];
        sWc3[u]  = make_float4(Wc3[u * 3 + 0], Wc3[u * 3 + 1],
                               Wc3[u * 3 + 2], 0.0f);
    }
    if (tid >= H && tid < H + 2) {
        int c = tid - H;
        float s = b2[c];
        #pragma unroll 8
        for (int j = 0; j < H; j++) s += W2[j * 2 + c];
        sS[c] = s;
    }
    if (tid < NCLS) sbc3[tid] = bc3[tid];
    for (int i = tid; i < TT - 1; i += 128)
        sdt[i] = tg[i + 1] - tg[i];
    for (int i = tid; i < H * H; i += 128) {
        int k = i >> 6, j = i & 63;     // Wc2 row-major [k][j]
        sWc2T[j][k] = Wc2[i];
    }
    __syncthreads();

    const int gid = blockIdx.x * 128 + tid;
    const int eA = gid >> 2;            // first element
    const int q  = gid & 3;             // quad slot
    const int half = B >> 1;
    if (eA >= half) return;             // never true for B=65536 (exact grid)
    const int eB = eA + half;

    float yaA = y0g[eA * 2 + 0], ybA = y0g[eA * 2 + 1];
    float yaB = y0g[eB * 2 + 0], ybB = y0g[eB * 2 + 1];
    const float S0 = sS[0], S1 = sS[1];

    // Register-stage loop-invariant V pairs for groups 0,1.
    u64 Vst[8];
    #pragma unroll
    for (int g = 0; g < 2; g++) {
        const int base = PK(g, q, 0);
        const ulonglong2 a = *(const ulonglong2*)&sVV[base * 2];
        const ulonglong2 b = *(const ulonglong2*)&sVV[base * 2 + 4];
        Vst[g * 4 + 0] = a.x; Vst[g * 4 + 1] = a.y;
        Vst[g * 4 + 2] = b.x; Vst[g * 4 + 3] = b.y;
    }

    // ------------------------------ 63 Euler steps ------------------------
    for (int s = 0; s < TT - 1; s++) {
        const float dt = sdt[s];
        const u64 pAa = pk2(yaA, yaA), pAb = pk2(ybA, ybA);
        const u64 pBa = pk2(yaB, yaB), pBb = pk2(ybB, ybB);
        u64 accA = 0, accB = 0;

        #pragma unroll
        for (int g = 0; g < 4; g++) {
            const int base = PK(g, q, 0);
            const ulonglong2 WA = *(const ulonglong2*)&sWA[base];
            const ulonglong2 WB = *(const ulonglong2*)&sWB[base];
            const ulonglong2 BB = *(const ulonglong2*)&sBB[base];
            u64 V01x, V01y, V23x, V23y;
            if (g < 2) {
                V01x = Vst[g * 4 + 0]; V01y = Vst[g * 4 + 1];
                V23x = Vst[g * 4 + 2]; V23y = Vst[g * 4 + 3];
            } else {
                const ulonglong2 Vp01 = *(const ulonglong2*)&sVV[base * 2];
                const ulonglong2 Vp23 = *(const ulonglong2*)&sVV[base * 2 + 4];
                V01x = Vp01.x; V01y = Vp01.y;
                V23x = Vp23.x; V23y = Vp23.y;
            }

            // element A
            {
                u64 w01 = fma2(pAa, WA.x, fma2(pAb, WB.x, BB.x));
                u64 w23 = fma2(pAa, WA.y, fma2(pAb, WB.y, BB.y));
                float w0, w1, w2, w3;
                unpk2(w01, w0, w1);
                unpk2(w23, w2, w3);
                w0 = fminf(w0, 30.0f); w1 = fminf(w1, 30.0f);
                w2 = fminf(w2, 30.0f); w3 = fminf(w3, 30.0f);
                float E0 = fast_ex2(w0), E1 = fast_ex2(w1);
                float E2 = fast_ex2(w2), E3 = fast_ex2(w3);
                float a0 = E0 + 1.0f, a2 = E2 + 1.0f;
                float p01 = fmaf(a0, E1, a0);
                float p23 = fmaf(a2, E3, a2);
                float rinv = fast_rcp(p01 * p23);
                float q01 = rinv * p23, q23 = rinv * p01;
                float r1 = q01 * a0, r0 = fmaf(q01, E1, q01);
                float r3 = q23 * a2, r2 = fmaf(q23, E3, q23);
                accA = fma2(pk2(r0, r0), V01x, accA);
                accA = fma2(pk2(r1, r1), V01y, accA);
                accA = fma2(pk2(r2, r2), V23x, accA);
                accA = fma2(pk2(r3, r3), V23y, accA);
            }
            // element B
            {
                u64 w01 = fma2(pBa, WA.x, fma2(pBb, WB.x, BB.x));
                u64 w23 = fma2(pBa, WA.y, fma2(pBb, WB.y, BB.y));
                float w0, w1, w2, w3;
                unpk2(w01, w0, w1);
                unpk2(w23, w2, w3);
                w0 = fminf(w0, 30.0f); w1 = fminf(w1, 30.0f);
                w2 = fminf(w2, 30.0f); w3 = fminf(w3, 30.0f);
                float E0 = fast_ex2(w0), E1 = fast_ex2(w1);
                float E2 = fast_ex2(w2), E3 = fast_ex2(w3);
                float a0 = E0 + 1.0f, a2 = E2 + 1.0f;
                float p01 = fmaf(a0, E1, a0);
                float p23 = fmaf(a2, E3, a2);
                float rinv = fast_rcp(p01 * p23);
                float q01 = rinv * p23, q23 = rinv * p01;
                float r1 = q01 * a0, r0 = fmaf(q01, E1, q01);
                float r3 = q23 * a2, r2 = fmaf(q23, E3, q23);
                accB = fma2(pk2(r0, r0), V01x, accB);
                accB = fma2(pk2(r1, r1), V01y, accB);
                accB = fma2(pk2(r2, r2), V23x, accB);
                accB = fma2(pk2(r3, r3), V23y, accB);
            }
        }

        float accA0, accA1, accB0, accB1;
        unpk2(accA, accA0, accA1);
        unpk2(accB, accB0, accB1);
        accA0 += __shfl_xor_sync(0xffffffffu, accA0, 1);
        accA0 += __shfl_xor_sync(0xffffffffu, accA0, 2);
        accA1 += __shfl_xor_sync(0xffffffffu, accA1, 1);
        accA1 += __shfl_xor_sync(0xffffffffu, accA1, 2);
        accB0 += __shfl_xor_sync(0xffffffffu, accB0, 1);
        accB0 += __shfl_xor_sync(0xffffffffu, accB0, 2);
        accB1 += __shfl_xor_sync(0xffffffffu, accB1, 1);
        accB1 += __shfl_xor_sync(0xffffffffu, accB1, 2);

        yaA = fmaf(dt, S0 + accA0, yaA);   // identical across the quad
        ybA = fmaf(dt, S1 + accA1, ybA);
        yaB = fmaf(dt, S0 + accB0, yaB);
        ybB = fmaf(dt, S1 + accB1, ybB);
    }

    // ------------------------------ fused classifier ----------------------
    const int eloc = tid >> 2;             // sH1 row for this quad
    const int k0 = 16 * q;

    #pragma unroll
    for (int m = 0; m < 2; m++) {
        const float ya = (m == 0) ? yaA : yaB;
        const float yb = (m == 0) ? ybA : ybB;
        const int e   = (m == 0) ? eA : eB;

        __syncwarp();                      // protect sH1 reuse between elems
        // lane q builds its h1 slice k in [16q, 16q+16)
        #pragma unroll
        for (int i = 0; i < 16; i += 4) {
            const float4 wa = *(const float4*)&sWc1A[k0 + i];
            const float4 wb = *(const float4*)&sWc1B[k0 + i];
            const float4 bb = *(const float4*)&sbc1[k0 + i];
            float4 h;
            h.x = fmaxf(fmaf(ya, wa.x, fmaf(yb, wb.x, bb.x)), 0.0f);
            h.y = fmaxf(fmaf(ya, wa.y, fmaf(yb, wb.y, bb.y)), 0.0f);
            h.z = fmaxf(fmaf(ya, wa.z, fmaf(yb, wb.z, bb.z)), 0.0f);
            h.w = fmaxf(fmaf(ya, wa.w, fmaf(yb, wb.w, bb.w)), 0.0f);
            *(float4*)&sH1[eloc][k0 + i] = h;
        }
        __syncwarp();                      // quad lanes share a warp

        // lane q owns output units j = 4*jj + q
        float acc[16];
        #pragma unroll
        for (int jj = 0; jj < 16; jj++) acc[jj] = sbc2[4 * jj + q];

        #pragma unroll 4
        for (int k = 0; k < H; k += 4) {
            const float4 hk = *(const float4*)&sH1[eloc][k];
            #pragma unroll
            for (int jj = 0; jj < 16; jj++) {
                const float4 w = *(const float4*)&sWc2T[4 * jj + q][k];
                acc[jj] = fmaf(hk.w, w.w,
                          fmaf(hk.z, w.z,
                          fmaf(hk.y, w.y,
                          fmaf(hk.x, w.x, acc[jj]))));
            }
        }

        float o0 = 0.f, o1 = 0.f, o2 = 0.f;
        #pragma unroll
        for (int jj = 0; jj < 16; jj++) {
            const float hv = fmaxf(acc[jj], 0.0f);
            const float4 wc = sWc3[4 * jj + q];
            o0 = fmaf(hv, wc.x, o0);
            o1 = fmaf(hv, wc.y, o1);
            o2 = fmaf(hv, wc.z, o2);
        }
        o0 += __shfl_xor_sync(0xffffffffu, o0, 1);
        o0 += __shfl_xor_sync(0xffffffffu, o0, 2);
        o1 += __shfl_xor_sync(0xffffffffu, o1, 1);
        o1 += __shfl_xor_sync(0xffffffffu, o1, 2);
        o2 += __shfl_xor_sync(0xffffffffu, o2, 1);
        o2 += __shfl_xor_sync(0xffffffffu, o2, 2);

        if (q == 0) {
            out[e * 3 + 0] = o0 + sbc3[0];
            out[e * 3 + 1] = o1 + sbc3[1];
            out[e * 3 + 2] = o2 + sbc3[2];
        }
    }
}

extern "C" void kernel_launch(void* const* d_in, const int* in_sizes, int n_in,
                              void* d_out, int out_size) {
    const float* y0  = (const float*)d_in[0];
    const float* t   = (const float*)d_in[1];
    const float* W1  = (const float*)d_in[2];
    const float* b1  = (const float*)d_in[3];
    const float* W2  = (const float*)d_in[4];
    const float* b2  = (const float*)d_in[5];
    const float* Wc1 = (const float*)d_in[6];
    const float* bc1 = (const float*)d_in[7];
    const float* Wc2 = (const float*)d_in[8];
    const float* bc2 = (const float*)d_in[9];
    const float* Wc3 = (const float*)d_in[10];
    const float* bc3 = (const float*)d_in[11];
    float* out = (float*)d_out;

    const int B = in_sizes[0] / 2;
    const long long th = (long long)B * 2;   // 4 lanes/elem, 2 elems/thread
    node_fused_kernel<<<(int)((th + 127) / 128), 128>>>(
        y0, t, W1, b1, W2, b2, Wc1, bc1, Wc2, bc2, Wc3, bc3, out, B);
}